// round 1
// baseline (speedup 1.0000x reference)
#include <cuda_runtime.h>
#include <math.h>

#define B_ 8
#define C_ 512
#define T_ 8192
#define P_ 512
#define K_ 30
#define M_ (B_ * P_)          // 4096 rows through the MLP

// output layout (concatenated tuple, fp32)
#define VIDEO_OFF 0
#define JOINT_OFF (VIDEO_OFF + B_ * K_)                 // 240
#define CLS_OFF   (JOINT_OFF + M_ * K_)                 // 123120
#define DET_OFF   (CLS_OFF + M_ * K_)                   // 246000
#define H7_OFF    (DET_OFF + M_ * K_)                   // 368880

// scratch (no cudaMalloc allowed)
__device__ float g_feats[M_ * C_];        // 8 MB  [4096,512]
__device__ float g_h6[M_ * 1024];         // 16 MB [4096,1024]
__device__ float g_cprob[M_ * K_];        // class softmax probs
__device__ float g_dmax[B_ * K_];
__device__ float g_dsum[B_ * K_];

// ---------------------------------------------------------------------------
// Kernel 1: per-(b,c) row scan in smem + answer all proposals
// grid = B*C blocks, 256 threads
// ---------------------------------------------------------------------------
__global__ void pool_kernel(const float* __restrict__ x,
                            const void* __restrict__ boxes_raw,
                            float* __restrict__ feats) {
    const int bc = blockIdx.x;
    const int b = bc / C_;
    const float* row = x + (size_t)bc * T_;

    __shared__ float cs[256 * 33];   // padded: chunk t at base t*33 (conflict-free scan)
    __shared__ float part[256];

    const int t = threadIdx.x;

    // coalesced load, padded smem write
    for (int j4 = t; j4 < T_ / 4; j4 += 256) {
        float4 v = reinterpret_cast<const float4*>(row)[j4];
        int j = j4 * 4;
        int base = (j >> 5) * 33 + (j & 31);
        cs[base + 0] = v.x; cs[base + 1] = v.y; cs[base + 2] = v.z; cs[base + 3] = v.w;
    }
    __syncthreads();

    // local sequential scan over this thread's 32 elements
    float run = 0.f;
    const int base = t * 33;
#pragma unroll
    for (int i = 0; i < 32; i++) { run += cs[base + i]; cs[base + i] = run; }
    part[t] = run;
    __syncthreads();

    // inclusive Hillis-Steele scan over the 256 partials
    for (int off = 1; off < 256; off <<= 1) {
        float v = part[t];
        float add = (t >= off) ? part[t - off] : 0.f;
        __syncthreads();
        part[t] = v + add;
        __syncthreads();
    }
    const float ofs = (t > 0) ? part[t - 1] : 0.f;
#pragma unroll
    for (int i = 0; i < 32; i++) cs[base + i] += ofs;
    __syncthreads();

    // detect box dtype from the first pair (safe read either way: >=16B array)
    const long long* b64all = (const long long*)boxes_raw;
    long long s0 = b64all[0], e0 = b64all[1];
    bool is64 = (s0 >= 0 && s0 < T_ && e0 >= 1 && e0 <= T_ && e0 > s0);

    for (int p = t; p < P_; p += 256) {
        int s, e;
        if (is64) {
            const long long* bb = b64all + (size_t)b * P_ * 2;
            s = (int)bb[2 * p]; e = (int)bb[2 * p + 1];
        } else {
            const int* bb = ((const int*)boxes_raw) + (size_t)b * P_ * 2;
            s = bb[2 * p]; e = bb[2 * p + 1];
        }
        int ei = e - 1;
        float ge = cs[(ei >> 5) * 33 + (ei & 31)];
        float gs = 0.f;
        if (s > 0) { int si = s - 1; gs = cs[(si >> 5) * 33 + (si & 31)]; }
        feats[((size_t)(b * P_ + p)) * C_ + (bc % C_)] = (ge - gs) / (float)(e - s);
    }
}

// ---------------------------------------------------------------------------
// Kernel 2: NT SGEMM, C = relu(A[M,K] * W[N,K]^T + bias), tiles 128x64x16
// 256 threads, 8x4 microtile per thread. M%128==0, N%64==0, K%16==0.
// ---------------------------------------------------------------------------
__global__ __launch_bounds__(256) void gemm_nt_relu(
    const float* __restrict__ A, const float* __restrict__ W,
    const float* __restrict__ bias, float* __restrict__ Cmat,
    int M, int N, int K) {
    __shared__ float As[16][128];
    __shared__ float Bs[16][64];

    const int tid = threadIdx.x;
    const int tx = tid & 15;   // n dir (4 cols each)
    const int ty = tid >> 4;   // m dir (8 rows each)

    const float* Aptr = A + (size_t)(blockIdx.y * 128) * K;
    const float* Wptr = W + (size_t)(blockIdx.x * 64) * K;

    float acc[8][4];
#pragma unroll
    for (int i = 0; i < 8; i++)
#pragma unroll
        for (int j = 0; j < 4; j++) acc[i][j] = 0.f;

    for (int k0 = 0; k0 < K; k0 += 16) {
        // load A tile: 128x16 = 512 float4, 2 per thread
#pragma unroll
        for (int u = 0; u < 2; u++) {
            int fid = tid + u * 256;
            int r = fid >> 2, kq = fid & 3;
            float4 v = *(const float4*)(Aptr + (size_t)r * K + k0 + kq * 4);
            As[kq * 4 + 0][r] = v.x; As[kq * 4 + 1][r] = v.y;
            As[kq * 4 + 2][r] = v.z; As[kq * 4 + 3][r] = v.w;
        }
        // load B tile: 64x16 = 256 float4, 1 per thread
        {
            int r = tid >> 2, kq = tid & 3;
            float4 v = *(const float4*)(Wptr + (size_t)r * K + k0 + kq * 4);
            Bs[kq * 4 + 0][r] = v.x; Bs[kq * 4 + 1][r] = v.y;
            Bs[kq * 4 + 2][r] = v.z; Bs[kq * 4 + 3][r] = v.w;
        }
        __syncthreads();

#pragma unroll
        for (int kk = 0; kk < 16; kk++) {
            float4 a0 = *(const float4*)&As[kk][ty * 8];
            float4 a1 = *(const float4*)&As[kk][ty * 8 + 4];
            float4 b0 = *(const float4*)&Bs[kk][tx * 4];
            float a[8] = {a0.x, a0.y, a0.z, a0.w, a1.x, a1.y, a1.z, a1.w};
            float bb[4] = {b0.x, b0.y, b0.z, b0.w};
#pragma unroll
            for (int i = 0; i < 8; i++)
#pragma unroll
                for (int j = 0; j < 4; j++) acc[i][j] = fmaf(a[i], bb[j], acc[i][j]);
        }
        __syncthreads();
    }

    const int n0 = blockIdx.x * 64 + tx * 4;
    const int m0 = blockIdx.y * 128 + ty * 8;
    float4 bv = *(const float4*)(bias + n0);
    float bb[4] = {bv.x, bv.y, bv.z, bv.w};
#pragma unroll
    for (int i = 0; i < 8; i++) {
        float4 o;
        o.x = fmaxf(acc[i][0] + bb[0], 0.f);
        o.y = fmaxf(acc[i][1] + bb[1], 0.f);
        o.z = fmaxf(acc[i][2] + bb[2], 0.f);
        o.w = fmaxf(acc[i][3] + bb[3], 0.f);
        *(float4*)(Cmat + (size_t)(m0 + i) * N + n0) = o;
    }
}

// ---------------------------------------------------------------------------
// Kernel 3: classifier heads + class softmax. 8 rows per block, 256 threads.
// ---------------------------------------------------------------------------
__device__ __forceinline__ float warp_sum(float v) {
#pragma unroll
    for (int o = 16; o > 0; o >>= 1) v += __shfl_xor_sync(0xffffffffu, v, o);
    return v;
}
__device__ __forceinline__ float warp_max(float v) {
#pragma unroll
    for (int o = 16; o > 0; o >>= 1) v = fmaxf(v, __shfl_xor_sync(0xffffffffu, v, o));
    return v;
}

__global__ __launch_bounds__(256) void heads_kernel(
    const float* __restrict__ h7,
    const float* __restrict__ Wc, const float* __restrict__ bc,
    const float* __restrict__ Wd, const float* __restrict__ bd,
    float* __restrict__ clsOut, float* __restrict__ detOut,
    float* __restrict__ cprob) {
    __shared__ float hs[8][512];
    __shared__ float cls[8][32];
    __shared__ float det[8][32];

    const int m0 = blockIdx.x * 8;
    const int tid = threadIdx.x;
    const int warp = tid >> 5, lane = tid & 31;

    for (int idx = tid; idx < 8 * 512; idx += 256)
        hs[idx >> 9][idx & 511] = h7[(size_t)(m0 + (idx >> 9)) * 512 + (idx & 511)];
    __syncthreads();

    for (int n = warp; n < K_; n += 8) {
        float aC[8] = {0, 0, 0, 0, 0, 0, 0, 0};
        float aD[8] = {0, 0, 0, 0, 0, 0, 0, 0};
#pragma unroll
        for (int i = 0; i < 16; i++) {
            int col = lane + 32 * i;
            float wc = Wc[n * 512 + col];
            float wd = Wd[n * 512 + col];
#pragma unroll
            for (int r = 0; r < 8; r++) {
                float h = hs[r][col];
                aC[r] = fmaf(h, wc, aC[r]);
                aD[r] = fmaf(h, wd, aD[r]);
            }
        }
#pragma unroll
        for (int r = 0; r < 8; r++) {
            float vc = warp_sum(aC[r]);
            float vd = warp_sum(aD[r]);
            if (lane == 0) { cls[r][n] = vc + bc[n]; det[r][n] = vd + bd[n]; }
        }
    }
    __syncthreads();

    // class softmax: warp r handles row r
    const int r = warp;
    float v = (lane < K_) ? cls[r][lane] : -INFINITY;
    float mx = warp_max(v);
    float e = (lane < K_) ? expf(v - mx) : 0.f;
    float sm = warp_sum(e);
    if (lane < K_) {
        size_t rowi = (size_t)(m0 + r);
        cprob[rowi * K_ + lane] = e / sm;
        clsOut[rowi * K_ + lane] = cls[r][lane];
        detOut[rowi * K_ + lane] = det[r][lane];
    }
}

// ---------------------------------------------------------------------------
// Kernel 4: det softmax stats per (b,k): max & sumexp over P. warp per (b,k).
// ---------------------------------------------------------------------------
__global__ void detstats_kernel(const float* __restrict__ detL) {
    const int gw = blockIdx.x * 8 + (threadIdx.x >> 5);
    if (gw >= B_ * K_) return;
    const int lane = threadIdx.x & 31;
    const int b = gw / K_, k = gw % K_;

    float vals[16];
    float mx = -INFINITY;
#pragma unroll
    for (int i = 0; i < 16; i++) {
        int p = lane + 32 * i;
        vals[i] = detL[((size_t)(b * P_ + p)) * K_ + k];
        mx = fmaxf(mx, vals[i]);
    }
    mx = warp_max(mx);
    float s = 0.f;
#pragma unroll
    for (int i = 0; i < 16; i++) s += expf(vals[i] - mx);
    s = warp_sum(s);
    if (lane == 0) { g_dmax[gw] = mx; g_dsum[gw] = s; }
}

// ---------------------------------------------------------------------------
// Kernel 5: joint = class_prob * det_prob, video = sum over P. block per (b,k).
// ---------------------------------------------------------------------------
__global__ __launch_bounds__(256) void joint_kernel(
    const float* __restrict__ detL, const float* __restrict__ cprob,
    float* __restrict__ joint, float* __restrict__ video) {
    const int bk = blockIdx.x;
    const int b = bk / K_, k = bk % K_;
    const float mx = g_dmax[bk];
    const float inv = 1.f / g_dsum[bk];

    __shared__ float red[256];
    float local = 0.f;
    for (int p = threadIdx.x; p < P_; p += 256) {
        size_t idx = ((size_t)(b * P_ + p)) * K_ + k;
        float dp = expf(detL[idx] - mx) * inv;
        float j = cprob[idx] * dp;
        joint[idx] = j;
        local += j;
    }
    red[threadIdx.x] = local;
    __syncthreads();
    for (int s = 128; s > 0; s >>= 1) {
        if (threadIdx.x < s) red[threadIdx.x] += red[threadIdx.x + s];
        __syncthreads();
    }
    if (threadIdx.x == 0) video[bk] = red[0];
}

// ---------------------------------------------------------------------------
extern "C" void kernel_launch(void* const* d_in, const int* in_sizes, int n_in,
                              void* d_out, int out_size) {
    const float* x  = (const float*)d_in[0];
    const void*  bx = d_in[1];                  // int32 or int64 boxes (auto-detected)
    const float* W6 = (const float*)d_in[2];
    const float* b6 = (const float*)d_in[3];
    const float* W7 = (const float*)d_in[4];
    const float* b7 = (const float*)d_in[5];
    const float* Wc = (const float*)d_in[6];
    const float* bc = (const float*)d_in[7];
    const float* Wd = (const float*)d_in[8];
    const float* bd = (const float*)d_in[9];
    float* out = (float*)d_out;

    float* feats; cudaGetSymbolAddress((void**)&feats, g_feats);
    float* h6;    cudaGetSymbolAddress((void**)&h6, g_h6);
    float* cprob; cudaGetSymbolAddress((void**)&cprob, g_cprob);

    float* h7    = out + H7_OFF;
    float* clsO  = out + CLS_OFF;
    float* detO  = out + DET_OFF;
    float* joint = out + JOINT_OFF;
    float* video = out + VIDEO_OFF;

    // 1. pooled features [4096, 512]
    pool_kernel<<<B_ * C_, 256>>>(x, bx, feats);

    // 2. h6 = relu(feats @ W6^T + b6) : M=4096, N=1024, K=512
    {
        dim3 grid(1024 / 64, M_ / 128);
        gemm_nt_relu<<<grid, 256>>>(feats, W6, b6, h6, M_, 1024, 512);
    }
    // 3. h7 = relu(h6 @ W7^T + b7) : M=4096, N=512, K=1024  -> output
    {
        dim3 grid(512 / 64, M_ / 128);
        gemm_nt_relu<<<grid, 256>>>(h6, W7, b7, h7, M_, 512, 1024);
    }
    // 4. heads + class softmax
    heads_kernel<<<M_ / 8, 256>>>(h7, Wc, bc, Wd, bd, clsO, detO, cprob);

    // 5. det softmax stats per (b,k)
    detstats_kernel<<<(B_ * K_ + 7) / 8, 256>>>(detO);

    // 6. joint & video
    joint_kernel<<<B_ * K_, 256>>>(detO, cprob, joint, video);
}

// round 3
// speedup vs baseline: 1.0496x; 1.0496x over previous
#include <cuda_runtime.h>
#include <math.h>
#include <stdint.h>

#define B_ 8
#define C_ 512
#define T_ 8192
#define P_ 512
#define K_ 30
#define M_ (B_ * P_)          // 4096 rows through the MLP

// output layout (concatenated tuple, fp32)
#define VIDEO_OFF 0
#define JOINT_OFF (VIDEO_OFF + B_ * K_)                 // 240
#define CLS_OFF   (JOINT_OFF + M_ * K_)                 // 123120
#define DET_OFF   (CLS_OFF + M_ * K_)                   // 246000
#define H7_OFF    (DET_OFF + M_ * K_)                   // 368880

// ------------------------- scratch (no cudaMalloc) -------------------------
__device__ float g_pooled[B_ * C_ * P_];   // 8 MB  [B*C, P]
__device__ float g_feats[M_ * C_];         // 8 MB  [4096, 512]
__device__ float g_h6[M_ * 1024];          // 16 MB [4096, 1024]
__device__ float g_whd[64 * 512];          // packed head weights
__device__ float g_bhd[64];
__device__ float g_ghd[M_ * 64];           // head logits (cls|det|pad)
__device__ float g_cprob[M_ * K_];
__device__ float g_dmax[B_ * K_], g_dsum[B_ * K_];

// ------------------------- f32x2 helpers -------------------------
__device__ __forceinline__ unsigned long long pack2(float a) {
    unsigned long long r;
    asm("mov.b64 %0, {%1, %1};" : "=l"(r) : "f"(a));
    return r;
}
__device__ __forceinline__ void ffma2(unsigned long long& d,
                                      unsigned long long a, unsigned long long b) {
    asm("fma.rn.f32x2 %0, %1, %2, %0;" : "+l"(d) : "l"(a), "l"(b));
}
__device__ __forceinline__ void unpack2(unsigned long long d, float& lo, float& hi) {
    asm("mov.b64 {%0, %1}, %2;" : "=f"(lo), "=f"(hi) : "l"(d));
}

__device__ __forceinline__ float warp_sum(float v) {
#pragma unroll
    for (int o = 16; o > 0; o >>= 1) v += __shfl_xor_sync(0xffffffffu, v, o);
    return v;
}
__device__ __forceinline__ float warp_max(float v) {
#pragma unroll
    for (int o = 16; o > 0; o >>= 1) v = fmaxf(v, __shfl_xor_sync(0xffffffffu, v, o));
    return v;
}

// ---------------------------------------------------------------------------
// Kernel 1: per-(b,c) row scan in smem + answer all proposals (coalesced out)
// ---------------------------------------------------------------------------
__global__ void pool_kernel(const float* __restrict__ x,
                            const void* __restrict__ boxes_raw,
                            float* __restrict__ pooled) {
    const int bc = blockIdx.x;
    const int b = bc / C_;
    const float* row = x + (size_t)bc * T_;

    __shared__ float cs[256 * 33];
    __shared__ float part[256];
    const int t = threadIdx.x;

    for (int j4 = t; j4 < T_ / 4; j4 += 256) {
        float4 v = reinterpret_cast<const float4*>(row)[j4];
        int j = j4 * 4;
        int base = (j >> 5) * 33 + (j & 31);
        cs[base + 0] = v.x; cs[base + 1] = v.y; cs[base + 2] = v.z; cs[base + 3] = v.w;
    }
    __syncthreads();

    float run = 0.f;
    const int base = t * 33;
#pragma unroll
    for (int i = 0; i < 32; i++) { run += cs[base + i]; cs[base + i] = run; }
    part[t] = run;
    __syncthreads();
    for (int off = 1; off < 256; off <<= 1) {
        float v = part[t];
        float add = (t >= off) ? part[t - off] : 0.f;
        __syncthreads();
        part[t] = v + add;
        __syncthreads();
    }
    const float ofs = (t > 0) ? part[t - 1] : 0.f;
#pragma unroll
    for (int i = 0; i < 32; i++) cs[base + i] += ofs;
    __syncthreads();

    const long long* b64all = (const long long*)boxes_raw;
    long long s0 = b64all[0], e0 = b64all[1];
    bool is64 = (s0 >= 0 && s0 < T_ && e0 >= 1 && e0 <= T_ && e0 > s0);

    for (int p = t; p < P_; p += 256) {
        int s, e;
        if (is64) {
            const long long* bb = b64all + (size_t)b * P_ * 2;
            s = (int)bb[2 * p]; e = (int)bb[2 * p + 1];
        } else {
            const int* bb = ((const int*)boxes_raw) + (size_t)b * P_ * 2;
            s = bb[2 * p]; e = bb[2 * p + 1];
        }
        int ei = e - 1;
        float ge = cs[(ei >> 5) * 33 + (ei & 31)];
        float gs = 0.f;
        if (s > 0) { int si = s - 1; gs = cs[(si >> 5) * 33 + (si & 31)]; }
        pooled[(size_t)bc * P_ + p] = (ge - gs) / (float)(e - s);
    }
}

// ---------------------------------------------------------------------------
// Kernel 2: transpose [B,C,P] -> [B*P, C]
// ---------------------------------------------------------------------------
__global__ void transpose_k(const float* __restrict__ pooled,
                            float* __restrict__ feats) {
    __shared__ float t[32][33];
    const int b = blockIdx.z, c0 = blockIdx.x * 32, p0 = blockIdx.y * 32;
    const int tx = threadIdx.x, ty = threadIdx.y;
#pragma unroll
    for (int i = 0; i < 32; i += 8)
        t[ty + i][tx] = pooled[((size_t)(b * C_ + c0 + ty + i)) * P_ + p0 + tx];
    __syncthreads();
#pragma unroll
    for (int i = 0; i < 32; i += 8)
        feats[((size_t)(b * P_ + p0 + ty + i)) * C_ + c0 + tx] = t[tx][ty + i];
}

// Kernel 3: pack Wc,Wd -> 64x512 padded head weight + bias
__global__ void prep_whd(const float* __restrict__ Wc, const float* __restrict__ bc,
                         const float* __restrict__ Wd, const float* __restrict__ bd,
                         float* __restrict__ wo, float* __restrict__ bo) {
    int i = blockIdx.x * blockDim.x + threadIdx.x;
    if (i < 64 * 512) {
        int r = i >> 9, k = i & 511;
        wo[i] = (r < 30) ? Wc[r * 512 + k] : ((r < 60) ? Wd[(r - 30) * 512 + k] : 0.f);
    }
    if (i < 64) bo[i] = (i < 30) ? bc[i] : ((i < 60) ? bd[i - 30] : 0.f);
}

// ---------------------------------------------------------------------------
// f32x2 packed NT SGEMM: C[M,N] = act(A[M,K] @ W[N,K]^T + bias)
// BM=128, BK=16. BN=128: 16x16 threads, 8x8 microtile.
//                BN=64 :  8x32 threads, 4x8 microtile.
// ---------------------------------------------------------------------------
template <int BN, bool RELU>
__global__ __launch_bounds__(256, 2) void gemm_f32x2(
    const float* __restrict__ A, const float* __restrict__ W,
    const float* __restrict__ bias, float* __restrict__ Cmat,
    int K, int ldC) {
    constexpr int TX = BN / 8;          // threads along n (each does 8 n)
    constexpr int TY = 256 / TX;        // threads along m
    constexpr int MT = 128 / TY;        // m per thread
    constexpr int NA = 2;               // A float4 loads per thread (128*16/1024)
    constexpr int NB = (BN * 16) / 1024;

    __shared__ float As[16][128];
    __shared__ float Bs[16][BN];

    const int tid = threadIdx.x;
    const int tx = tid % TX, ty = tid / TX;
    const int m0 = blockIdx.y * 128, n0 = blockIdx.x * BN;

    const float* Ag = A + (size_t)m0 * K;
    const float* Wg = W + (size_t)n0 * K;

    float4 pa[NA], pb[NB];

    unsigned long long acc[MT][4];
#pragma unroll
    for (int i = 0; i < MT; i++)
#pragma unroll
        for (int j = 0; j < 4; j++) acc[i][j] = 0ull;

    // prologue: load tile 0
#pragma unroll
    for (int u = 0; u < NA; u++) {
        int fid = tid + u * 256, r = fid >> 2, q = fid & 3;
        pa[u] = *(const float4*)(Ag + (size_t)r * K + q * 4);
    }
#pragma unroll
    for (int u = 0; u < NB; u++) {
        int fid = tid + u * 256, r = fid >> 2, q = fid & 3;
        pb[u] = *(const float4*)(Wg + (size_t)r * K + q * 4);
    }
#pragma unroll
    for (int u = 0; u < NA; u++) {
        int fid = tid + u * 256, r = fid >> 2, q = fid & 3;
        As[q * 4 + 0][r] = pa[u].x; As[q * 4 + 1][r] = pa[u].y;
        As[q * 4 + 2][r] = pa[u].z; As[q * 4 + 3][r] = pa[u].w;
    }
#pragma unroll
    for (int u = 0; u < NB; u++) {
        int fid = tid + u * 256, r = fid >> 2, q = fid & 3;
        Bs[q * 4 + 0][r] = pb[u].x; Bs[q * 4 + 1][r] = pb[u].y;
        Bs[q * 4 + 2][r] = pb[u].z; Bs[q * 4 + 3][r] = pb[u].w;
    }
    __syncthreads();

    const int NIT = K >> 4;
    for (int it = 0; it < NIT; it++) {
        const bool more = (it + 1 < NIT);
        if (more) {
            const int k0 = (it + 1) << 4;
#pragma unroll
            for (int u = 0; u < NA; u++) {
                int fid = tid + u * 256, r = fid >> 2, q = fid & 3;
                pa[u] = *(const float4*)(Ag + (size_t)r * K + k0 + q * 4);
            }
#pragma unroll
            for (int u = 0; u < NB; u++) {
                int fid = tid + u * 256, r = fid >> 2, q = fid & 3;
                pb[u] = *(const float4*)(Wg + (size_t)r * K + k0 + q * 4);
            }
        }

#pragma unroll
        for (int kk = 0; kk < 16; kk++) {
            float av[MT];
            {
                float4 a0 = *(const float4*)&As[kk][ty * MT];
                av[0] = a0.x; av[1] = a0.y; av[2] = a0.z; av[3] = a0.w;
                if (MT == 8) {
                    float4 a1 = *(const float4*)&As[kk][ty * MT + 4];
                    av[4] = a1.x; av[5] = a1.y; av[6] = a1.z; av[7] = a1.w;
                }
            }
            ulonglong2 t0 = *(const ulonglong2*)&Bs[kk][tx * 8];
            ulonglong2 t1 = *(const ulonglong2*)&Bs[kk][tx * 8 + 4];
            unsigned long long bv[4] = {t0.x, t0.y, t1.x, t1.y};
#pragma unroll
            for (int i = 0; i < MT; i++) {
                unsigned long long a2 = pack2(av[i]);
#pragma unroll
                for (int j = 0; j < 4; j++) ffma2(acc[i][j], a2, bv[j]);
            }
        }

        if (more) {
            __syncthreads();
#pragma unroll
            for (int u = 0; u < NA; u++) {
                int fid = tid + u * 256, r = fid >> 2, q = fid & 3;
                As[q * 4 + 0][r] = pa[u].x; As[q * 4 + 1][r] = pa[u].y;
                As[q * 4 + 2][r] = pa[u].z; As[q * 4 + 3][r] = pa[u].w;
            }
#pragma unroll
            for (int u = 0; u < NB; u++) {
                int fid = tid + u * 256, r = fid >> 2, q = fid & 3;
                Bs[q * 4 + 0][r] = pb[u].x; Bs[q * 4 + 1][r] = pb[u].y;
                Bs[q * 4 + 2][r] = pb[u].z; Bs[q * 4 + 3][r] = pb[u].w;
            }
            __syncthreads();
        }
    }

    // epilogue
    float bb[8];
    {
        float4 b0 = *(const float4*)(bias + n0 + tx * 8);
        float4 b1 = *(const float4*)(bias + n0 + tx * 8 + 4);
        bb[0] = b0.x; bb[1] = b0.y; bb[2] = b0.z; bb[3] = b0.w;
        bb[4] = b1.x; bb[5] = b1.y; bb[6] = b1.z; bb[7] = b1.w;
    }
#pragma unroll
    for (int i = 0; i < MT; i++) {
        float o[8];
#pragma unroll
        for (int j = 0; j < 4; j++) unpack2(acc[i][j], o[2 * j], o[2 * j + 1]);
#pragma unroll
        for (int c = 0; c < 8; c++) {
            o[c] += bb[c];
            if (RELU) o[c] = fmaxf(o[c], 0.f);
        }
        float* dst = Cmat + (size_t)(m0 + ty * MT + i) * ldC + n0 + tx * 8;
        *(float4*)(dst) = make_float4(o[0], o[1], o[2], o[3]);
        *(float4*)(dst + 4) = make_float4(o[4], o[5], o[6], o[7]);
    }
}

// ---------------------------------------------------------------------------
// heads postprocess: per-row class softmax + split cls/det
// ---------------------------------------------------------------------------
__global__ __launch_bounds__(256) void headpost_kernel(
    const float* __restrict__ ghd, float* __restrict__ clsO,
    float* __restrict__ detO, float* __restrict__ cprob) {
    const int row = blockIdx.x * 8 + (threadIdx.x >> 5);
    const int lane = threadIdx.x & 31;
    const bool act = lane < K_;
    float c = act ? ghd[(size_t)row * 64 + lane] : -INFINITY;
    float d = act ? ghd[(size_t)row * 64 + K_ + lane] : 0.f;
    float mx = warp_max(c);
    float e = act ? expf(c - mx) : 0.f;
    float s = warp_sum(e);
    if (act) {
        clsO[(size_t)row * K_ + lane] = c;
        detO[(size_t)row * K_ + lane] = d;
        cprob[(size_t)row * K_ + lane] = e / s;
    }
}

// det softmax stats per (b,k)
__global__ void detstats_kernel(const float* __restrict__ detL) {
    const int gw = blockIdx.x * 8 + (threadIdx.x >> 5);
    if (gw >= B_ * K_) return;
    const int lane = threadIdx.x & 31;
    const int b = gw / K_, k = gw % K_;
    float vals[16];
    float mx = -INFINITY;
#pragma unroll
    for (int i = 0; i < 16; i++) {
        int p = lane + 32 * i;
        vals[i] = detL[((size_t)(b * P_ + p)) * K_ + k];
        mx = fmaxf(mx, vals[i]);
    }
    mx = warp_max(mx);
    float s = 0.f;
#pragma unroll
    for (int i = 0; i < 16; i++) s += expf(vals[i] - mx);
    s = warp_sum(s);
    if (lane == 0) { g_dmax[gw] = mx; g_dsum[gw] = s; }
}

__global__ __launch_bounds__(256) void joint_kernel(
    const float* __restrict__ detL, const float* __restrict__ cprob,
    float* __restrict__ joint, float* __restrict__ video) {
    const int bk = blockIdx.x;
    const int b = bk / K_, k = bk % K_;
    const float mx = g_dmax[bk];
    const float inv = 1.f / g_dsum[bk];
    __shared__ float red[256];
    float local = 0.f;
    for (int p = threadIdx.x; p < P_; p += 256) {
        size_t idx = ((size_t)(b * P_ + p)) * K_ + k;
        float dp = expf(detL[idx] - mx) * inv;
        float j = cprob[idx] * dp;
        joint[idx] = j;
        local += j;
    }
    red[threadIdx.x] = local;
    __syncthreads();
    for (int s = 128; s > 0; s >>= 1) {
        if (threadIdx.x < s) red[threadIdx.x] += red[threadIdx.x + s];
        __syncthreads();
    }
    if (threadIdx.x == 0) video[bk] = red[0];
}

// ---------------------------------------------------------------------------
extern "C" void kernel_launch(void* const* d_in, const int* in_sizes, int n_in,
                              void* d_out, int out_size) {
    const float* x  = (const float*)d_in[0];
    const void*  bx = d_in[1];
    const float* W6 = (const float*)d_in[2];
    const float* b6 = (const float*)d_in[3];
    const float* W7 = (const float*)d_in[4];
    const float* b7 = (const float*)d_in[5];
    const float* Wc = (const float*)d_in[6];
    const float* bc = (const float*)d_in[7];
    const float* Wd = (const float*)d_in[8];
    const float* bd = (const float*)d_in[9];
    float* out = (float*)d_out;

    float *pooled, *feats, *h6, *whd, *bhd, *ghd, *cprob;
    cudaGetSymbolAddress((void**)&pooled, g_pooled);
    cudaGetSymbolAddress((void**)&feats, g_feats);
    cudaGetSymbolAddress((void**)&h6, g_h6);
    cudaGetSymbolAddress((void**)&whd, g_whd);
    cudaGetSymbolAddress((void**)&bhd, g_bhd);
    cudaGetSymbolAddress((void**)&ghd, g_ghd);
    cudaGetSymbolAddress((void**)&cprob, g_cprob);

    float* h7    = out + H7_OFF;
    float* clsO  = out + CLS_OFF;
    float* detO  = out + DET_OFF;
    float* joint = out + JOINT_OFF;
    float* video = out + VIDEO_OFF;

    // 1. pooled [B*C, P]
    pool_kernel<<<B_ * C_, 256>>>(x, bx, pooled);
    // 2. feats [M, C]
    transpose_k<<<dim3(C_ / 32, P_ / 32, B_), dim3(32, 8)>>>(pooled, feats);
    // 3. packed head weights
    prep_whd<<<(64 * 512 + 255) / 256, 256>>>(Wc, bc, Wd, bd, whd, bhd);

    // 4. h6 = relu(feats @ W6^T + b6) : M=4096, N=1024, K=512
    gemm_f32x2<128, true><<<dim3(8, 32), 256>>>(feats, W6, b6, h6, 512, 1024);
    // 5. h7 = relu(h6 @ W7^T + b7) : M=4096, N=512, K=1024 -> out
    gemm_f32x2<128, true><<<dim3(4, 32), 256>>>(h6, W7, b7, h7, 1024, 512);
    // 6. heads: ghd = h7 @ Whd^T + bhd : M=4096, N=64, K=512
    gemm_f32x2<64, false><<<dim3(1, 32), 256>>>(h7, whd, bhd, ghd, 512, 64);

    // 7. class softmax + split
    headpost_kernel<<<M_ / 8, 256>>>(ghd, clsO, detO, cprob);
    // 8. det softmax stats
    detstats_kernel<<<(B_ * K_ + 7) / 8, 256>>>(detO);
    // 9. joint & video
    joint_kernel<<<B_ * K_, 256>>>(detO, cprob, joint, video);
}